// round 2
// baseline (speedup 1.0000x reference)
#include <cuda_runtime.h>

// ---------------- problem constants ----------------
#define N_SRC0 200000
#define N_DST0 50000
#define N_DST1 10000
#define E0_N   800000
#define E1_N   160000
#define NPAIR  5000
// feature dims: IN = HID = OUT = 256, NB = 4 (64x64 blocks)

// ---------------- scratch (static device globals; no allocation) ----------------
// g_t is reused: layer-0 transform (200000x256) then layer-1 transform (50000x256).
__device__ float g_t[(size_t)N_SRC0 * 256];
__device__ float g_agg0[(size_t)N_DST0 * 256];
__device__ float g_h1[(size_t)N_DST0 * 256];
__device__ float g_agg1[(size_t)N_DST1 * 256];

// ---------------- packed f32x2 helpers ----------------
__device__ __forceinline__ void fma2(unsigned long long& d, unsigned long long a,
                                     unsigned long long b) {
    asm("fma.rn.f32x2 %0, %1, %2, %0;" : "+l"(d) : "l"(a), "l"(b));
}
__device__ __forceinline__ void unpack2(unsigned long long v, float& lo, float& hi) {
    asm("mov.b64 {%0, %1}, %2;" : "=f"(lo), "=f"(hi) : "l"(v));
}

// Scratch selector so kernels can address __device__ globals without any host
// cudaGetSymbolAddress call (kernel_launch stays launches-only).
__device__ __forceinline__ float* scratch_ptr(int which) {
    switch (which) {
        case 0: return g_t;
        case 1: return g_agg0;
        case 2: return g_h1;
        default: return g_agg1;
    }
}

// ---------------- generic tiled GEMM ----------------
// C[M,N] = A[M,K] @ B[K,N]   (optionally fused: C = relu(C + Add + bias))
// Block tile 64x64, BK=16, 256 threads, thread tile 4x4 via f32x2 pairs.
// blockIdx.z batches with element strides sA/sB/sC (for block-diagonal transform).
// A/C/Add may come from scratch globals (selector >= 0) or external pointers.
template <bool FUSED>
__global__ __launch_bounds__(256)
void gemm_kernel(const float* __restrict__ Aext, int Asel,
                 const float* __restrict__ B,
                 float* __restrict__ Cext, int Csel,
                 int AddSel, const float* __restrict__ bias,
                 int M, int N, int K, int lda, int ldb, int ldc,
                 int sA, int sB, int sC)
{
    const float* A = (Asel >= 0) ? scratch_ptr(Asel) : Aext;
    float*       C = (Csel >= 0) ? scratch_ptr(Csel) : Cext;
    const float* Add = FUSED ? scratch_ptr(AddSel) : nullptr;

    const int bz = blockIdx.z;
    A += (size_t)bz * sA;
    B += (size_t)bz * sB;
    C += (size_t)bz * sC;

    __shared__ __align__(16) float As[16][128]; // duplicated: As[k][2m]=As[k][2m+1]=A[m][k]
    __shared__ __align__(16) float Bs[16][64];

    const int tid  = threadIdx.x;
    const int row0 = blockIdx.x * 64;
    const int col0 = blockIdx.y * 64;
    const int ty = tid >> 4;          // 0..15 -> rows ty*4..ty*4+3
    const int tx = tid & 15;          // 0..15 -> cols tx*4..tx*4+3

    const int arow = tid >> 2;        // 0..63
    const int acol = (tid & 3) * 4;   // 0,4,8,12
    const int brow = tid >> 4;        // 0..15
    const int bcol = (tid & 15) * 4;  // 0..60

    unsigned long long acc[4][2];
    #pragma unroll
    for (int r = 0; r < 4; r++) { acc[r][0] = 0ull; acc[r][1] = 0ull; }

    for (int k0 = 0; k0 < K; k0 += 16) {
        // load A tile (rows row0+arow, cols k0+acol..+3), duplicated into As
        float4 av = make_float4(0.f, 0.f, 0.f, 0.f);
        if (row0 + arow < M)
            av = *(const float4*)&A[(size_t)(row0 + arow) * lda + k0 + acol];
        {
            float2 d;
            d.x = d.y = av.x; *(float2*)&As[acol + 0][2 * arow] = d;
            d.x = d.y = av.y; *(float2*)&As[acol + 1][2 * arow] = d;
            d.x = d.y = av.z; *(float2*)&As[acol + 2][2 * arow] = d;
            d.x = d.y = av.w; *(float2*)&As[acol + 3][2 * arow] = d;
        }
        // load B tile (row k0+brow, cols col0+bcol..+3)
        *(float4*)&Bs[brow][bcol] =
            *(const float4*)&B[(size_t)(k0 + brow) * ldb + col0 + bcol];
        __syncthreads();

        #pragma unroll
        for (int kk = 0; kk < 16; kk++) {
            const unsigned long long* ap =
                (const unsigned long long*)&As[kk][ty * 8];
            const unsigned long long* bp =
                (const unsigned long long*)&Bs[kk][tx * 4];
            unsigned long long b0 = bp[0], b1 = bp[1];
            unsigned long long a0 = ap[0], a1 = ap[1], a2 = ap[2], a3 = ap[3];
            fma2(acc[0][0], a0, b0); fma2(acc[0][1], a0, b1);
            fma2(acc[1][0], a1, b0); fma2(acc[1][1], a1, b1);
            fma2(acc[2][0], a2, b0); fma2(acc[2][1], a2, b1);
            fma2(acc[3][0], a3, b0); fma2(acc[3][1], a3, b1);
        }
        __syncthreads();
    }

    // epilogue
    const int gc = col0 + tx * 4;
    float4 bb = make_float4(0.f, 0.f, 0.f, 0.f);
    if (FUSED) bb = *(const float4*)&bias[gc];
    #pragma unroll
    for (int r = 0; r < 4; r++) {
        int gr = row0 + ty * 4 + r;
        if (gr < M) {
            float c0, c1, c2, c3;
            unpack2(acc[r][0], c0, c1);
            unpack2(acc[r][1], c2, c3);
            if (FUSED) {
                const float4 ad = *(const float4*)&Add[(size_t)gr * 256 + gc];
                c0 = fmaxf(c0 + ad.x + bb.x, 0.f);
                c1 = fmaxf(c1 + ad.y + bb.y, 0.f);
                c2 = fmaxf(c2 + ad.z + bb.z, 0.f);
                c3 = fmaxf(c3 + ad.w + bb.w, 0.f);
            }
            *(float4*)&C[(size_t)gr * ldc + gc] = make_float4(c0, c1, c2, c3);
        }
    }
}

// ---------------- zero fill (scratch selector) ----------------
__global__ void zero_kernel(int sel, int n4)
{
    float4* p = (float4*)scratch_ptr(sel);
    int i = blockIdx.x * blockDim.x + threadIdx.x;
    int stride = gridDim.x * blockDim.x;
    for (; i < n4; i += stride) p[i] = make_float4(0.f, 0.f, 0.f, 0.f);
}

// ---------------- edge scatter-add: agg[dst] += T[src] ----------------
// one thread per (edge, float4-chunk); 64 chunks per edge (256 floats)
__global__ void scatter_kernel(int Tsel, const int* __restrict__ src,
                               const int* __restrict__ dst,
                               int AggSel, int E)
{
    const float* T = scratch_ptr(Tsel);
    float* agg = scratch_ptr(AggSel);
    long long idx = (long long)blockIdx.x * blockDim.x + threadIdx.x;
    const long long total = (long long)E * 64;
    const long long stride = (long long)gridDim.x * blockDim.x;
    for (; idx < total; idx += stride) {
        int e = (int)(idx >> 6);
        int c = (int)(idx & 63);
        int s = __ldg(src + e);
        int d = __ldg(dst + e);
        float4 v = ((const float4*)T)[(size_t)s * 64 + c];
        float* p = agg + (size_t)d * 256 + c * 4;
        atomicAdd(p + 0, v.x);
        atomicAdd(p + 1, v.y);
        atomicAdd(p + 2, v.z);
        atomicAdd(p + 3, v.w);
    }
}

// ---------------- link-prediction MLP ----------------
// e = h[a] * h[b];  y = relu(e @ pw1 + pb1);  out = y @ pw2 + pb2
// one block (128 threads) per pair; blocks [0,5000)=pos, [5000,10000)=neg
__global__ __launch_bounds__(128)
void pred_kernel(const float* __restrict__ h,
                 const int* __restrict__ ps, const int* __restrict__ pd,
                 const int* __restrict__ ns, const int* __restrict__ nd,
                 const float* __restrict__ pw1, const float* __restrict__ pb1,
                 const float* __restrict__ pw2, const float* __restrict__ pb2,
                 float* __restrict__ out)
{
    const int pair = blockIdx.x;
    const bool pos = pair < NPAIR;
    const int i = pos ? pair : pair - NPAIR;
    const int a = pos ? __ldg(ps + i) : __ldg(ns + i);
    const int b = pos ? __ldg(pd + i) : __ldg(nd + i);
    const int tid = threadIdx.x;

    __shared__ float e[256];
    e[tid]       = h[(size_t)a * 256 + tid]       * h[(size_t)b * 256 + tid];
    e[tid + 128] = h[(size_t)a * 256 + tid + 128] * h[(size_t)b * 256 + tid + 128];
    __syncthreads();

    float acc = pb1[tid];
    #pragma unroll 8
    for (int c = 0; c < 256; c++)
        acc = fmaf(e[c], pw1[c * 128 + tid], acc);
    acc = fmaxf(acc, 0.f) * pw2[tid];

    #pragma unroll
    for (int o = 16; o > 0; o >>= 1)
        acc += __shfl_down_sync(0xffffffffu, acc, o);
    __shared__ float red[4];
    if ((tid & 31) == 0) red[tid >> 5] = acc;
    __syncthreads();
    if (tid == 0)
        out[pair] = red[0] + red[1] + red[2] + red[3] + pb2[0];
}

// ---------------- launcher (kernel launches ONLY) ----------------
extern "C" void kernel_launch(void* const* d_in, const int* in_sizes, int n_in,
                              void* d_out, int out_size)
{
    const float* x        = (const float*)d_in[0];
    const int*   src0     = (const int*)d_in[1];
    const int*   dst0     = (const int*)d_in[2];
    const int*   src1     = (const int*)d_in[3];
    const int*   dst1     = (const int*)d_in[4];
    const int*   pos_src  = (const int*)d_in[5];
    const int*   pos_dst  = (const int*)d_in[6];
    const int*   neg_src  = (const int*)d_in[7];
    const int*   neg_dst  = (const int*)d_in[8];
    const float* W0       = (const float*)d_in[9];
    const float* loop0    = (const float*)d_in[10];
    const float* b0       = (const float*)d_in[11];
    const float* W1       = (const float*)d_in[12];
    const float* loop1    = (const float*)d_in[13];
    const float* b1       = (const float*)d_in[14];
    const float* pw1      = (const float*)d_in[15];
    const float* pb1      = (const float*)d_in[16];
    const float* pw2      = (const float*)d_in[17];
    const float* pb2      = (const float*)d_in[18];
    float* out = (float*)d_out;

    // scratch selectors: 0=g_t, 1=g_agg0, 2=g_h1, 3=g_agg1
    const dim3 blk(256);

    // Layer 0: block-diagonal transform  t = bdd(x, W0)  (4 batched 64-col GEMMs)
    gemm_kernel<false><<<dim3((N_SRC0 + 63) / 64, 1, 4), blk>>>(
        x, -1, W0, nullptr, 0, -1, nullptr,
        N_SRC0, 64, 64, 256, 64, 256, 64, 64 * 64, 64);

    // agg0 = segment_sum(t[src0], dst0)
    zero_kernel<<<4096, 256>>>(1, N_DST0 * 64);
    scatter_kernel<<<32768, 256>>>(0, src0, dst0, 1, E0_N);

    // h1 = relu(agg0 + x[:50000] @ loop0 + b0)
    gemm_kernel<true><<<dim3((N_DST0 + 63) / 64, 4, 1), blk>>>(
        x, -1, loop0, nullptr, 2, 1, b0,
        N_DST0, 256, 256, 256, 256, 256, 0, 0, 0);

    // Layer 1: t = bdd(h1, W1)  (reuses g_t)
    gemm_kernel<false><<<dim3((N_DST0 + 63) / 64, 1, 4), blk>>>(
        nullptr, 2, W1, nullptr, 0, -1, nullptr,
        N_DST0, 64, 64, 256, 64, 256, 64, 64 * 64, 64);

    // agg1 = segment_sum(t[src1], dst1)
    zero_kernel<<<2048, 256>>>(3, N_DST1 * 64);
    scatter_kernel<<<16384, 256>>>(0, src1, dst1, 3, E1_N);

    // h2 = relu(agg1 + h1[:10000] @ loop1 + b1) -> written directly into d_out
    float* h2 = out + 2 * NPAIR;
    gemm_kernel<true><<<dim3((N_DST1 + 63) / 64, 4, 1), blk>>>(
        nullptr, 2, loop1, h2, -1, 3, b1,
        N_DST1, 256, 256, 256, 256, 256, 0, 0, 0);

    // link prediction: out[0:5000]=pos, out[5000:10000]=neg
    pred_kernel<<<2 * NPAIR, 128>>>(h2, pos_src, pos_dst, neg_src, neg_dst,
                                    pw1, pb1, pw2, pb2, out);
}

// round 3
// speedup vs baseline: 1.4218x; 1.4218x over previous
#include <cuda_runtime.h>

// ---------------- problem constants ----------------
#define N_SRC0 200000
#define N_DST0 50000
#define N_DST1 10000
#define E0_N   800000
#define E1_N   160000
#define NPAIR  5000
// feature dims: IN = HID = OUT = 256, NB = 4 (64x64 blocks)

// ---------------- scratch (static device globals; no allocation) ----------------
// g_t is reused: layer-0 transform (200000x256) then layer-1 transform (50000x256).
__device__ float g_t[(size_t)N_SRC0 * 256];
__device__ float g_agg0[(size_t)N_DST0 * 256];
__device__ float g_h1[(size_t)N_DST0 * 256];
__device__ float g_agg1[(size_t)N_DST1 * 256];
// CSR scratch (sized for layer 0; reused for layer 1)
__device__ int g_cnt[N_DST0 + 1];   // counts -> row starts (exclusive scan in place)
__device__ int g_cursor[N_DST0];    // fill cursors
__device__ int g_eid[E0_N];         // src node per CSR slot

__device__ __forceinline__ float* scratch_ptr(int which) {
    switch (which) {
        case 0: return g_t;
        case 1: return g_agg0;
        case 2: return g_h1;
        default: return g_agg1;
    }
}

// ---------------- packed f32x2 helpers ----------------
__device__ __forceinline__ void fma2(unsigned long long& d, unsigned long long a,
                                     unsigned long long b) {
    asm("fma.rn.f32x2 %0, %1, %2, %0;" : "+l"(d) : "l"(a), "l"(b));
}
__device__ __forceinline__ void unpack2(unsigned long long v, float& lo, float& hi) {
    asm("mov.b64 {%0, %1}, %2;" : "=f"(lo), "=f"(hi) : "l"(v));
}

// ---------------- tiled GEMM, 128xBN block tile, 8x(BN/16) thread tile ----------------
// C[M,N] = A[M,K] @ B[K,N]; FUSED: C = relu(C + Add + bias).
// 256 threads (16x16), BK=16. A stored duplicated in smem so f32x2 pairs load directly.
// blockIdx.z batches with element strides sA/sB/sC (block-diagonal transform).
template <int BN, bool FUSED>
__global__ __launch_bounds__(256, 2)
void gemm_kernel(const float* __restrict__ Aext, int Asel,
                 const float* __restrict__ B,
                 float* __restrict__ Cext, int Csel,
                 int AddSel, const float* __restrict__ bias,
                 int M, int K, int lda, int ldb, int ldc,
                 int sA, int sB, int sC)
{
    constexpr int TN  = BN / 16;   // cols per thread (8 or 4)
    constexpr int TNP = TN / 2;    // f32x2 pairs per thread (4 or 2)

    const float* A = (Asel >= 0) ? scratch_ptr(Asel) : Aext;
    float*       C = (Csel >= 0) ? scratch_ptr(Csel) : Cext;
    const float* Add = FUSED ? scratch_ptr(AddSel) : nullptr;

    const int bz = blockIdx.z;
    A += (size_t)bz * sA;
    B += (size_t)bz * sB;
    C += (size_t)bz * sC;

    __shared__ __align__(16) float As[16][256]; // duplicated pairs: As[k][2m]=As[k][2m+1]=A[m][k]
    __shared__ __align__(16) float Bs[16][BN];

    const int tid  = threadIdx.x;
    const int row0 = blockIdx.x * 128;
    const int col0 = blockIdx.y * BN;
    const int ty = tid >> 4;          // 0..15 -> rows ty*8 .. +7
    const int tx = tid & 15;          // 0..15 -> cols tx*TN .. +TN-1

    // A tile load mapping: each thread loads 8 consecutive cols of one row
    const int aRow = tid & 127;
    const int aCol = (tid >> 7) * 8;

    unsigned long long acc[8][TNP];
    #pragma unroll
    for (int i = 0; i < 8; i++)
        #pragma unroll
        for (int j = 0; j < TNP; j++) acc[i][j] = 0ull;

    for (int k0 = 0; k0 < K; k0 += 16) {
        // ---- load A tile (guarded rows), store duplicated ----
        float4 av0 = make_float4(0.f, 0.f, 0.f, 0.f);
        float4 av1 = make_float4(0.f, 0.f, 0.f, 0.f);
        if (row0 + aRow < M) {
            const float* ap = &A[(size_t)(row0 + aRow) * lda + k0 + aCol];
            av0 = *(const float4*)(ap);
            av1 = *(const float4*)(ap + 4);
        }
        {
            float2 d;
            d.x = d.y = av0.x; *(float2*)&As[aCol + 0][2 * aRow] = d;
            d.x = d.y = av0.y; *(float2*)&As[aCol + 1][2 * aRow] = d;
            d.x = d.y = av0.z; *(float2*)&As[aCol + 2][2 * aRow] = d;
            d.x = d.y = av0.w; *(float2*)&As[aCol + 3][2 * aRow] = d;
            d.x = d.y = av1.x; *(float2*)&As[aCol + 4][2 * aRow] = d;
            d.x = d.y = av1.y; *(float2*)&As[aCol + 5][2 * aRow] = d;
            d.x = d.y = av1.z; *(float2*)&As[aCol + 6][2 * aRow] = d;
            d.x = d.y = av1.w; *(float2*)&As[aCol + 7][2 * aRow] = d;
        }
        // ---- load B tile ----
        if (BN == 128) {
            const int bRow = tid >> 4, bCol = (tid & 15) * 8;
            const float* bp = &B[(size_t)(k0 + bRow) * ldb + col0 + bCol];
            *(float4*)&Bs[bRow][bCol]     = *(const float4*)(bp);
            *(float4*)&Bs[bRow][bCol + 4] = *(const float4*)(bp + 4);
        } else {
            const int bRow = tid >> 4, bCol = (tid & 15) * 4;
            *(float4*)&Bs[bRow][bCol] =
                *(const float4*)&B[(size_t)(k0 + bRow) * ldb + col0 + bCol];
        }
        __syncthreads();

        #pragma unroll
        for (int kk = 0; kk < 16; kk++) {
            ulonglong2 a01 = *(const ulonglong2*)&As[kk][ty * 16];
            ulonglong2 a23 = *(const ulonglong2*)&As[kk][ty * 16 + 4];
            ulonglong2 a45 = *(const ulonglong2*)&As[kk][ty * 16 + 8];
            ulonglong2 a67 = *(const ulonglong2*)&As[kk][ty * 16 + 12];
            unsigned long long ar[8] = {a01.x, a01.y, a23.x, a23.y,
                                        a45.x, a45.y, a67.x, a67.y};
            unsigned long long br[TNP];
            {
                ulonglong2 b01 = *(const ulonglong2*)&Bs[kk][tx * TN];
                br[0] = b01.x; br[1] = b01.y;
                if (TNP == 4) {
                    ulonglong2 b23 = *(const ulonglong2*)&Bs[kk][tx * TN + 4];
                    br[2] = b23.x; br[3] = b23.y;
                }
            }
            #pragma unroll
            for (int i = 0; i < 8; i++)
                #pragma unroll
                for (int j = 0; j < TNP; j++)
                    fma2(acc[i][j], ar[i], br[j]);
        }
        __syncthreads();
    }

    // ---- epilogue ----
    const int gc = col0 + tx * TN;
    float bb[TN];
    if (FUSED) {
        #pragma unroll
        for (int j = 0; j < TN; j++) bb[j] = bias[gc + j];
    }
    #pragma unroll
    for (int i = 0; i < 8; i++) {
        const int gr = row0 + ty * 8 + i;
        if (gr >= M) continue;
        float c[TN];
        #pragma unroll
        for (int j = 0; j < TNP; j++) unpack2(acc[i][j], c[2 * j], c[2 * j + 1]);
        if (FUSED) {
            const float* arow = &Add[(size_t)gr * 256 + gc];
            #pragma unroll
            for (int j = 0; j < TN; j++)
                c[j] = fmaxf(c[j] + arow[j] + bb[j], 0.f);
        }
        float* crow = &C[(size_t)gr * ldc + gc];
        #pragma unroll
        for (int j = 0; j < TNP; j++)
            *(float2*)(crow + 2 * j) = make_float2(c[2 * j], c[2 * j + 1]);
    }
}

// ---------------- CSR build ----------------
__global__ void zero_int_kernel(int n)
{
    int i = blockIdx.x * blockDim.x + threadIdx.x;
    if (i < n) g_cnt[i] = 0;
}

__global__ void hist_kernel(const int* __restrict__ dst, int E)
{
    int e = blockIdx.x * blockDim.x + threadIdx.x;
    if (e < E) atomicAdd(&g_cnt[dst[e]], 1);
}

// single-block exclusive scan of g_cnt[0..n-1] in place; writes g_cnt[n]=total
// and copies row starts into g_cursor.
__global__ __launch_bounds__(1024)
void scan_kernel(int n)
{
    __shared__ int s[1024];
    __shared__ int carry;
    const int tid = threadIdx.x;
    if (tid == 0) carry = 0;
    __syncthreads();
    for (int base = 0; base < n; base += 1024) {
        int v = (base + tid < n) ? g_cnt[base + tid] : 0;
        s[tid] = v;
        __syncthreads();
        #pragma unroll
        for (int off = 1; off < 1024; off <<= 1) {
            int t = (tid >= off) ? s[tid - off] : 0;
            __syncthreads();
            s[tid] += t;
            __syncthreads();
        }
        int exc = carry + s[tid] - v;
        if (base + tid < n) { g_cnt[base + tid] = exc; g_cursor[base + tid] = exc; }
        __syncthreads();
        if (tid == 0) carry += s[1023];
        __syncthreads();
    }
    if (tid == 0) g_cnt[n] = carry;
}

__global__ void fill_kernel(const int* __restrict__ src,
                            const int* __restrict__ dst, int E)
{
    int e = blockIdx.x * blockDim.x + threadIdx.x;
    if (e < E) {
        int pos = atomicAdd(&g_cursor[dst[e]], 1);
        g_eid[pos] = src[e];
    }
}

// ---------------- CSR gather: agg[r] = sum over edges of T[src] ----------------
// one block of 64 threads per dst row; each thread owns one float4 chunk (256 floats)
__global__ __launch_bounds__(64)
void gather_kernel(int Tsel, int AggSel)
{
    const float4* T = (const float4*)scratch_ptr(Tsel);
    float4* agg = (float4*)scratch_ptr(AggSel);
    const int r = blockIdx.x;
    const int tid = threadIdx.x;
    const int start = g_cnt[r], end = g_cnt[r + 1];

    __shared__ int se[64];
    float4 acc = make_float4(0.f, 0.f, 0.f, 0.f);
    for (int base = start; base < end; base += 64) {
        const int m = min(64, end - base);
        if (tid < m) se[tid] = g_eid[base + tid];
        __syncthreads();
        for (int j = 0; j < m; j++) {
            float4 v = T[(size_t)se[j] * 64 + tid];
            acc.x += v.x; acc.y += v.y; acc.z += v.z; acc.w += v.w;
        }
        __syncthreads();
    }
    agg[(size_t)r * 64 + tid] = acc;
}

// ---------------- link-prediction MLP ----------------
__global__ __launch_bounds__(128)
void pred_kernel(const float* __restrict__ h,
                 const int* __restrict__ ps, const int* __restrict__ pd,
                 const int* __restrict__ ns, const int* __restrict__ nd,
                 const float* __restrict__ pw1, const float* __restrict__ pb1,
                 const float* __restrict__ pw2, const float* __restrict__ pb2,
                 float* __restrict__ out)
{
    const int pair = blockIdx.x;
    const bool pos = pair < NPAIR;
    const int i = pos ? pair : pair - NPAIR;
    const int a = pos ? __ldg(ps + i) : __ldg(ns + i);
    const int b = pos ? __ldg(pd + i) : __ldg(nd + i);
    const int tid = threadIdx.x;

    __shared__ float e[256];
    e[tid]       = h[(size_t)a * 256 + tid]       * h[(size_t)b * 256 + tid];
    e[tid + 128] = h[(size_t)a * 256 + tid + 128] * h[(size_t)b * 256 + tid + 128];
    __syncthreads();

    float acc = pb1[tid];
    #pragma unroll 8
    for (int c = 0; c < 256; c++)
        acc = fmaf(e[c], pw1[c * 128 + tid], acc);
    acc = fmaxf(acc, 0.f) * pw2[tid];

    #pragma unroll
    for (int o = 16; o > 0; o >>= 1)
        acc += __shfl_down_sync(0xffffffffu, acc, o);
    __shared__ float red[4];
    if ((tid & 31) == 0) red[tid >> 5] = acc;
    __syncthreads();
    if (tid == 0)
        out[pair] = red[0] + red[1] + red[2] + red[3] + pb2[0];
}

// ---------------- launcher (kernel launches ONLY) ----------------
extern "C" void kernel_launch(void* const* d_in, const int* in_sizes, int n_in,
                              void* d_out, int out_size)
{
    const float* x        = (const float*)d_in[0];
    const int*   src0     = (const int*)d_in[1];
    const int*   dst0     = (const int*)d_in[2];
    const int*   src1     = (const int*)d_in[3];
    const int*   dst1     = (const int*)d_in[4];
    const int*   pos_src  = (const int*)d_in[5];
    const int*   pos_dst  = (const int*)d_in[6];
    const int*   neg_src  = (const int*)d_in[7];
    const int*   neg_dst  = (const int*)d_in[8];
    const float* W0       = (const float*)d_in[9];
    const float* loop0    = (const float*)d_in[10];
    const float* b0       = (const float*)d_in[11];
    const float* W1       = (const float*)d_in[12];
    const float* loop1    = (const float*)d_in[13];
    const float* b1       = (const float*)d_in[14];
    const float* pw1      = (const float*)d_in[15];
    const float* pb1      = (const float*)d_in[16];
    const float* pw2      = (const float*)d_in[17];
    const float* pb2      = (const float*)d_in[18];
    float* out = (float*)d_out;

    const dim3 blk(256);
    // scratch selectors: 0=g_t, 1=g_agg0, 2=g_h1, 3=g_agg1

    // Layer 0: t = bdd(x, W0)  (4 batched 64-col GEMMs)
    gemm_kernel<64, false><<<dim3((N_SRC0 + 127) / 128, 1, 4), blk>>>(
        x, -1, W0, nullptr, 0, -1, nullptr,
        N_SRC0, 64, 256, 64, 256, 64, 64 * 64, 64);

    // CSR build for (dst0): counts -> scan -> fill
    zero_int_kernel<<<(N_DST0 + 256) / 256, 256>>>(N_DST0 + 1);
    hist_kernel<<<(E0_N + 255) / 256, 256>>>(dst0, E0_N);
    scan_kernel<<<1, 1024>>>(N_DST0);
    fill_kernel<<<(E0_N + 255) / 256, 256>>>(src0, dst0, E0_N);
    // agg0 = segment_sum(t[src0], dst0)
    gather_kernel<<<N_DST0, 64>>>(0, 1);

    // h1 = relu(agg0 + x[:50000] @ loop0 + b0)
    gemm_kernel<128, true><<<dim3((N_DST0 + 127) / 128, 2, 1), blk>>>(
        x, -1, loop0, nullptr, 2, 1, b0,
        N_DST0, 256, 256, 256, 256, 0, 0, 0);

    // Layer 1: t = bdd(h1, W1)  (reuses g_t)
    gemm_kernel<64, false><<<dim3((N_DST0 + 127) / 128, 1, 4), blk>>>(
        nullptr, 2, W1, nullptr, 0, -1, nullptr,
        N_DST0, 64, 256, 64, 256, 64, 64 * 64, 64);

    // CSR build for (dst1)
    zero_int_kernel<<<(N_DST1 + 256) / 256, 256>>>(N_DST1 + 1);
    hist_kernel<<<(E1_N + 255) / 256, 256>>>(dst1, E1_N);
    scan_kernel<<<1, 1024>>>(N_DST1);
    fill_kernel<<<(E1_N + 255) / 256, 256>>>(src1, dst1, E1_N);
    gather_kernel<<<N_DST1, 64>>>(0, 3);

    // h2 = relu(agg1 + h1[:10000] @ loop1 + b1) -> directly into d_out
    float* h2 = out + 2 * NPAIR;
    gemm_kernel<128, true><<<dim3((N_DST1 + 127) / 128, 2, 1), blk>>>(
        nullptr, 2, loop1, h2, -1, 3, b1,
        N_DST1, 256, 256, 256, 256, 0, 0, 0);

    // link prediction: out[0:5000]=pos, out[5000:10000]=neg
    pred_kernel<<<2 * NPAIR, 128>>>(h2, pos_src, pos_dst, neg_src, neg_dst,
                                    pw1, pb1, pw2, pb2, out);
}